// round 5
// baseline (speedup 1.0000x reference)
#include <cuda_runtime.h>
#include <cuda_bf16.h>
#include <cstdint>
#include <math.h>

#define NNODES 100000
#define NEDGES 3200000
#define FIN    512
#define FHID   256
#define NCLS   40

// ---------------- device scratch ----------------
__device__ float g_H0[(size_t)NNODES * FHID];   // x @ W1
__device__ float g_P [(size_t)NNODES * NCLS];   // relu(spmm+b1) @ W2
__device__ int   g_deg[NNODES];
__device__ int   g_rowptr[NNODES + 1];
__device__ int   g_fill[NNODES];
__device__ int   g_bsum[128];
__device__ int   g_boff[128];
__device__ int   g_ccol[NEDGES];
__device__ float g_cval[NEDGES];
__device__ int   g_is64;
// W1 split into tf32 hi/lo (fp32 bit patterns), layout [FIN][FHID]
__device__ uint32_t g_W1h[(size_t)FIN * FHID];
__device__ uint32_t g_W1l[(size_t)FIN * FHID];

// ---------------- helpers ----------------
__device__ __forceinline__ uint32_t f2tf(float x) {
    uint32_t u; asm("cvt.rna.tf32.f32 %0, %1;" : "=r"(u) : "f"(x)); return u;
}

__device__ __forceinline__ void mma_tf32(float* d, const uint32_t* a, const uint32_t* b) {
    asm volatile(
      "mma.sync.aligned.m16n8k8.row.col.f32.tf32.tf32.f32 "
      "{%0,%1,%2,%3}, {%4,%5,%6,%7}, {%8,%9}, {%0,%1,%2,%3};\n"
      : "+f"(d[0]), "+f"(d[1]), "+f"(d[2]), "+f"(d[3])
      : "r"(a[0]), "r"(a[1]), "r"(a[2]), "r"(a[3]), "r"(b[0]), "r"(b[1]));
}

// ---------------- edge index width detection ----------------
__global__ void detect_kernel(const void* rowp) {
    if (threadIdx.x == 0 && blockIdx.x == 0) {
        const int* p = (const int*)rowp;
        int is64 = 1;
        for (int i = 0; i < 128; i++) {
            if (p[2 * i + 1] != 0) { is64 = 0; break; }
        }
        g_is64 = is64;
    }
}

__device__ __forceinline__ int load_idx(const void* p, int i, int is64) {
    return is64 ? (int)((const long long*)p)[i] : ((const int*)p)[i];
}

// ---------------- CSR build ----------------
__global__ void zero_deg_kernel() {
    int i = blockIdx.x * 1024 + threadIdx.x;
    if (i < NNODES) g_deg[i] = 0;
}

__global__ __launch_bounds__(256) void hist_kernel(const void* rowp) {
    int i = blockIdx.x * 256 + threadIdx.x;
    if (i >= NEDGES) return;
    int r = load_idx(rowp, i, g_is64);
    atomicAdd(&g_deg[r], 1);
}

__global__ __launch_bounds__(1024) void scan_k1_kernel() {
    __shared__ int sh[1024];
    int t = threadIdx.x;
    int i = blockIdx.x * 1024 + t;
    sh[t] = (i < NNODES) ? g_deg[i] : 0;
    __syncthreads();
    for (int off = 512; off > 0; off >>= 1) {
        if (t < off) sh[t] += sh[t + off];
        __syncthreads();
    }
    if (t == 0) g_bsum[blockIdx.x] = sh[0];
}

__global__ void scan_k2_kernel(int nblocks) {
    __shared__ int sh[128];
    int t = threadIdx.x;
    int x = (t < nblocks) ? g_bsum[t] : 0;
    sh[t] = x;
    __syncthreads();
    for (int off = 1; off < 128; off <<= 1) {
        int v = (t >= off) ? sh[t - off] : 0;
        __syncthreads();
        sh[t] += v;
        __syncthreads();
    }
    if (t < nblocks) g_boff[t] = sh[t] - x;
    if (t == 0) g_rowptr[NNODES] = NEDGES;
}

__global__ __launch_bounds__(1024) void scan_k3_kernel() {
    __shared__ int sh[1024];
    int t = threadIdx.x;
    int i = blockIdx.x * 1024 + t;
    int x = (i < NNODES) ? g_deg[i] : 0;
    sh[t] = x;
    __syncthreads();
    for (int off = 1; off < 1024; off <<= 1) {
        int v = (t >= off) ? sh[t - off] : 0;
        __syncthreads();
        sh[t] += v;
        __syncthreads();
    }
    if (i < NNODES) {
        int excl = sh[t] - x + g_boff[blockIdx.x];
        g_rowptr[i] = excl;
        g_fill[i]   = excl;
    }
}

__global__ __launch_bounds__(256) void scatter_kernel(const void* rowp, const void* colp,
                                                      const float* __restrict__ val) {
    int i = blockIdx.x * 256 + threadIdx.x;
    if (i >= NEDGES) return;
    int is64 = g_is64;
    int r = load_idx(rowp, i, is64);
    int c = load_idx(colp, i, is64);
    int pos = atomicAdd(&g_fill[r], 1);
    g_ccol[pos] = c;
    g_cval[pos] = val[i];
}

// ---------------- W1 tf32 hi/lo pre-split --------------------------------
__global__ __launch_bounds__(256) void w1cvt_kernel(const float* __restrict__ W1) {
    int i = blockIdx.x * 256 + threadIdx.x;
    if (i >= FIN * FHID) return;
    float v = W1[i];
    uint32_t h = f2tf(v);
    uint32_t l = f2tf(v - __uint_as_float(h));
    g_W1h[i] = h;
    g_W1l[i] = l;
}

// ---------------- GEMM1 (tf32 split, operands pre-split in smem) --------
// g_H0 = x @ W1, M=100000, K=512, N=256. Block 128x128, BK=16, 8 warps.
// smem (uint32 units): AsH[2][128][20], AsL, BsH[2][16][136], BsL
#define ASZ  2560                 // 128*20
#define BSZ  2176                 // 16*136
#define OFF_ASL  (2 * ASZ)        // 5120
#define OFF_BSH  (4 * ASZ)        // 10240
#define OFF_BSL  (4 * ASZ + 2 * BSZ)
#define G1_SMEM_BYTES ((4 * ASZ + 4 * BSZ) * 4)   // 75776

__global__ __launch_bounds__(256) void gemm1_tf32_kernel(const float* __restrict__ A) {
    extern __shared__ uint32_t usm[];
    uint32_t* AsH = usm;
    uint32_t* AsL = usm + OFF_ASL;
    uint32_t* BsH = usm + OFF_BSH;
    uint32_t* BsL = usm + OFF_BSL;

    const int tid  = threadIdx.x;
    const int lane = tid & 31;
    const int wid  = tid >> 5;
    const int wm   = wid & 3;       // 0..3  (M)
    const int wn   = wid >> 2;      // 0..1  (N)
    const int bm   = blockIdx.y * 128;
    const int bn   = blockIdx.x * 128;

    const int g  = lane >> 2;       // 0..7
    const int tg = lane & 3;        // 0..3

    float acc[2][8][4];
    #pragma unroll
    for (int i = 0; i < 2; i++)
        #pragma unroll
        for (int j = 0; j < 8; j++)
            #pragma unroll
            for (int q = 0; q < 4; q++) acc[i][j][q] = 0.f;

    float4 aReg[2];
    uint4  bRegH[2], bRegL[2];

    // helper lambda-free store of A float4 -> hi/lo
    // prologue: tile 0
    #pragma unroll
    for (int i = 0; i < 2; i++) {
        int f = tid + i * 256;
        int row = f >> 2, c4 = f & 3;
        float4 v = make_float4(0.f, 0.f, 0.f, 0.f);
        if (bm + row < NNODES)
            v = *(const float4*)(A + (size_t)(bm + row) * FIN + c4 * 4);
        uint32_t* ph = AsH + row * 20 + c4 * 4;
        uint32_t* pl = AsL + row * 20 + c4 * 4;
        uint32_t h;
        h = f2tf(v.x); ph[0] = h; pl[0] = f2tf(v.x - __uint_as_float(h));
        h = f2tf(v.y); ph[1] = h; pl[1] = f2tf(v.y - __uint_as_float(h));
        h = f2tf(v.z); ph[2] = h; pl[2] = f2tf(v.z - __uint_as_float(h));
        h = f2tf(v.w); ph[3] = h; pl[3] = f2tf(v.w - __uint_as_float(h));
    }
    #pragma unroll
    for (int i = 0; i < 2; i++) {
        int f = tid + i * 256;
        int krow = f >> 5, c4 = f & 31;
        const size_t gi = (size_t)krow * FHID + bn + c4 * 4;
        *(uint4*)(BsH + krow * 136 + c4 * 4) = *(const uint4*)(g_W1h + gi);
        *(uint4*)(BsL + krow * 136 + c4 * 4) = *(const uint4*)(g_W1l + gi);
    }
    __syncthreads();

    const int NITER = FIN / 16;   // 32
    for (int it = 0; it < NITER; it++) {
        int s = it & 1;
        const uint32_t* aH = AsH + s * ASZ;
        const uint32_t* aL = AsL + s * ASZ;
        const uint32_t* bH = BsH + s * BSZ;
        const uint32_t* bL = BsL + s * BSZ;

        // prefetch next tile into regs
        if (it + 1 < NITER) {
            int k0 = (it + 1) * 16;
            #pragma unroll
            for (int i = 0; i < 2; i++) {
                int f = tid + i * 256;
                int row = f >> 2, c4 = f & 3;
                aReg[i] = make_float4(0.f, 0.f, 0.f, 0.f);
                if (bm + row < NNODES)
                    aReg[i] = *(const float4*)(A + (size_t)(bm + row) * FIN + k0 + c4 * 4);
                int krow = f >> 5, c4b = f & 31;
                const size_t gi = (size_t)(k0 + krow) * FHID + bn + c4b * 4;
                bRegH[i] = *(const uint4*)(g_W1h + gi);
                bRegL[i] = *(const uint4*)(g_W1l + gi);
            }
        }

        // compute: 2 k8 chunks, pure LDS + MMA
        #pragma unroll
        for (int c = 0; c < 2; c++) {
            const int k = c * 8 + tg;
            uint32_t ah[2][4], al[2][4];
            #pragma unroll
            for (int mt = 0; mt < 2; mt++) {
                int r0 = wm * 32 + mt * 16 + g;
                ah[mt][0] = aH[r0 * 20 + k];
                ah[mt][1] = aH[(r0 + 8) * 20 + k];
                ah[mt][2] = aH[r0 * 20 + k + 4];
                ah[mt][3] = aH[(r0 + 8) * 20 + k + 4];
                al[mt][0] = aL[r0 * 20 + k];
                al[mt][1] = aL[(r0 + 8) * 20 + k];
                al[mt][2] = aL[r0 * 20 + k + 4];
                al[mt][3] = aL[(r0 + 8) * 20 + k + 4];
            }
            #pragma unroll
            for (int nt = 0; nt < 8; nt++) {
                int n = wn * 64 + nt * 8 + g;
                uint32_t bh[2], bl[2];
                bh[0] = bH[k * 136 + n];
                bh[1] = bH[(k + 4) * 136 + n];
                bl[0] = bL[k * 136 + n];
                bl[1] = bL[(k + 4) * 136 + n];
                #pragma unroll
                for (int mt = 0; mt < 2; mt++) {
                    mma_tf32(acc[mt][nt], ah[mt], bl);
                    mma_tf32(acc[mt][nt], al[mt], bh);
                    mma_tf32(acc[mt][nt], ah[mt], bh);
                }
            }
        }

        // store next tile
        if (it + 1 < NITER) {
            int ns = (it + 1) & 1;
            uint32_t* naH = AsH + ns * ASZ;
            uint32_t* naL = AsL + ns * ASZ;
            uint32_t* nbH = BsH + ns * BSZ;
            uint32_t* nbL = BsL + ns * BSZ;
            #pragma unroll
            for (int i = 0; i < 2; i++) {
                int f = tid + i * 256;
                int row = f >> 2, c4 = f & 3;
                uint32_t* ph = naH + row * 20 + c4 * 4;
                uint32_t* pl = naL + row * 20 + c4 * 4;
                uint32_t h;
                h = f2tf(aReg[i].x); ph[0] = h; pl[0] = f2tf(aReg[i].x - __uint_as_float(h));
                h = f2tf(aReg[i].y); ph[1] = h; pl[1] = f2tf(aReg[i].y - __uint_as_float(h));
                h = f2tf(aReg[i].z); ph[2] = h; pl[2] = f2tf(aReg[i].z - __uint_as_float(h));
                h = f2tf(aReg[i].w); ph[3] = h; pl[3] = f2tf(aReg[i].w - __uint_as_float(h));
                int krow = f >> 5, c4b = f & 31;
                *(uint4*)(nbH + krow * 136 + c4b * 4) = bRegH[i];
                *(uint4*)(nbL + krow * 136 + c4b * 4) = bRegL[i];
            }
            __syncthreads();
        }
    }

    // epilogue
    #pragma unroll
    for (int mt = 0; mt < 2; mt++) {
        int r0 = bm + wm * 32 + mt * 16 + g;
        #pragma unroll
        for (int nt = 0; nt < 8; nt++) {
            int cc = bn + wn * 64 + nt * 8 + 2 * tg;
            if (r0 < NNODES)
                *(float2*)(g_H0 + (size_t)r0 * FHID + cc) =
                    make_float2(acc[mt][nt][0], acc[mt][nt][1]);
            if (r0 + 8 < NNODES)
                *(float2*)(g_H0 + (size_t)(r0 + 8) * FHID + cc) =
                    make_float2(acc[mt][nt][2], acc[mt][nt][3]);
        }
    }
}

// ---------------- SpMM1 + bias + relu + GEMM2 fused ---------------------
// warp/row CSR gather (H1 row in registers), then row @ W2 -> g_P.
// smem: shWT[40][260] fp32 (W2 transposed, padded) + red[8][40*33]
#define W2S 260
#define SP1_WT_SZ   (NCLS * W2S)          // 10400 floats
#define SP1_RED_SZ  (8 * NCLS * 33)       // 10560 floats
#define SP1_SMEM_BYTES ((SP1_WT_SZ + SP1_RED_SZ) * 4)   // 83840

__global__ __launch_bounds__(256) void spmm1_fused_kernel(
    const float* __restrict__ b1, const float* __restrict__ W2)
{
    extern __shared__ float fsm[];
    float* shWT = fsm;                 // [c][k] stride W2S
    float* red  = fsm + SP1_WT_SZ;     // [warp][c][lane] stride 33

    const int tid = threadIdx.x;
    for (int idx = tid; idx < FHID * NCLS; idx += 256) {
        int k = idx / NCLS, c = idx % NCLS;
        shWT[c * W2S + k] = W2[idx];
    }
    __syncthreads();

    const int warp = tid >> 5;
    const int lane = tid & 31;
    const int row  = blockIdx.x * 8 + warp;
    const int start = g_rowptr[row];
    const int end   = g_rowptr[row + 1];

    float4 a0 = make_float4(0.f, 0.f, 0.f, 0.f);
    float4 a1 = make_float4(0.f, 0.f, 0.f, 0.f);

    for (int e0 = start; e0 < end; e0 += 32) {
        int m = min(32, end - e0);
        int   c = 0;
        float v = 0.f;
        if (lane < m) { c = g_ccol[e0 + lane]; v = g_cval[e0 + lane]; }
        for (int j = 0; j < m; j++) {
            int   cj = __shfl_sync(0xFFFFFFFFu, c, j);
            float vj = __shfl_sync(0xFFFFFFFFu, v, j);
            const float4* s = (const float4*)(g_H0 + (size_t)cj * FHID);
            float4 f0 = s[lane];
            float4 f1 = s[lane + 32];
            a0.x = fmaf(vj, f0.x, a0.x); a0.y = fmaf(vj, f0.y, a0.y);
            a0.z = fmaf(vj, f0.z, a0.z); a0.w = fmaf(vj, f0.w, a0.w);
            a1.x = fmaf(vj, f1.x, a1.x); a1.y = fmaf(vj, f1.y, a1.y);
            a1.z = fmaf(vj, f1.z, a1.z); a1.w = fmaf(vj, f1.w, a1.w);
        }
    }

    // bias + relu (lane owns feats 4*lane..+3 and 128+4*lane..+3)
    float4 t0 = *(const float4*)(b1 + 4 * lane);
    float4 t1 = *(const float4*)(b1 + 128 + 4 * lane);
    a0.x = fmaxf(a0.x + t0.x, 0.f); a0.y = fmaxf(a0.y + t0.y, 0.f);
    a0.z = fmaxf(a0.z + t0.z, 0.f); a0.w = fmaxf(a0.w + t0.w, 0.f);
    a1.x = fmaxf(a1.x + t1.x, 0.f); a1.y = fmaxf(a1.y + t1.y, 0.f);
    a1.z = fmaxf(a1.z + t1.z, 0.f); a1.w = fmaxf(a1.w + t1.w, 0.f);

    // per-lane partial dot with W2 (k = 4*lane..+3 and 128+4*lane..+3)
    float* rb = red + warp * (NCLS * 33);
    #pragma unroll
    for (int c = 0; c < NCLS; c++) {
        float4 wa = *(const float4*)&shWT[c * W2S + 4 * lane];
        float4 wb = *(const float4*)&shWT[c * W2S + 128 + 4 * lane];
        float p;
        p = a0.x * wa.x;
        p = fmaf(a0.y, wa.y, p); p = fmaf(a0.z, wa.z, p); p = fmaf(a0.w, wa.w, p);
        p = fmaf(a1.x, wb.x, p); p = fmaf(a1.y, wb.y, p);
        p = fmaf(a1.z, wb.z, p); p = fmaf(a1.w, wb.w, p);
        rb[c * 33 + lane] = p;
    }
    __syncwarp();

    // transpose-reduce: lane sums column `lane` (and 32+lane for lane<8)
    float s0 = 0.f;
    #pragma unroll 8
    for (int j = 0; j < 32; j++) s0 += rb[lane * 33 + j];
    float* o = g_P + (size_t)row * NCLS;
    o[lane] = s0;
    if (lane < 8) {
        float s1 = 0.f;
        #pragma unroll 8
        for (int j = 0; j < 32; j++) s1 += rb[(32 + lane) * 33 + j];
        o[32 + lane] = s1;
    }
}

// ---------------- SpMM2 (CSR, warp/row) + bias + log_softmax ------------
__global__ __launch_bounds__(256) void spmm2_csr_kernel(const float* __restrict__ b2,
                                                        float* __restrict__ out) {
    int row  = blockIdx.x * 8 + (threadIdx.x >> 5);
    int lane = threadIdx.x & 31;
    int start = g_rowptr[row];
    int end   = g_rowptr[row + 1];

    float acc0 = 0.f, acc1 = 0.f;

    for (int e0 = start; e0 < end; e0 += 32) {
        int m = min(32, end - e0);
        int   c = 0;
        float v = 0.f;
        if (lane < m) { c = g_ccol[e0 + lane]; v = g_cval[e0 + lane]; }
        for (int j = 0; j < m; j++) {
            int   cj = __shfl_sync(0xFFFFFFFFu, c, j);
            float vj = __shfl_sync(0xFFFFFFFFu, v, j);
            const float* p = g_P + (size_t)cj * NCLS;
            float p0 = p[lane];
            float p1 = (lane < 8) ? p[32 + lane] : 0.f;
            acc0 = fmaf(vj, p0, acc0);
            acc1 = fmaf(vj, p1, acc1);
        }
    }

    float v0 = acc0 + b2[lane];
    float v1 = (lane < 8) ? (acc1 + b2[32 + lane]) : -INFINITY;

    float mx = fmaxf(v0, v1);
    #pragma unroll
    for (int off = 16; off > 0; off >>= 1)
        mx = fmaxf(mx, __shfl_xor_sync(0xFFFFFFFFu, mx, off));

    float s = expf(v0 - mx) + ((lane < 8) ? expf(v1 - mx) : 0.f);
    #pragma unroll
    for (int off = 16; off > 0; off >>= 1)
        s += __shfl_xor_sync(0xFFFFFFFFu, s, off);

    float ls = mx + logf(s);
    float* o = out + (size_t)row * NCLS;
    o[lane] = v0 - ls;
    if (lane < 8) o[32 + lane] = v1 - ls;
}

// ---------------- launch ----------------
extern "C" void kernel_launch(void* const* d_in, const int* in_sizes, int n_in,
                              void* d_out, int out_size) {
    const float* x    = (const float*)d_in[0];
    const void*  erow = d_in[1];
    const void*  ecol = d_in[2];
    const float* eval = (const float*)d_in[3];
    const float* W1   = (const float*)d_in[4];
    const float* b1   = (const float*)d_in[5];
    const float* W2   = (const float*)d_in[6];
    const float* b2   = (const float*)d_in[7];
    float* out = (float*)d_out;

    const int nchunks = (NNODES + 1023) / 1024;

    detect_kernel<<<1, 32>>>(erow);
    zero_deg_kernel<<<nchunks, 1024>>>();
    hist_kernel<<<NEDGES / 256, 256>>>(erow);
    scan_k1_kernel<<<nchunks, 1024>>>();
    scan_k2_kernel<<<1, 128>>>(nchunks);
    scan_k3_kernel<<<nchunks, 1024>>>();
    scatter_kernel<<<NEDGES / 256, 256>>>(erow, ecol, eval);

    w1cvt_kernel<<<(FIN * FHID + 255) / 256, 256>>>(W1);

    cudaFuncSetAttribute(gemm1_tf32_kernel,
                         cudaFuncAttributeMaxDynamicSharedMemorySize, G1_SMEM_BYTES);
    {
        dim3 grid(FHID / 128, (NNODES + 127) / 128);  // (2, 782)
        gemm1_tf32_kernel<<<grid, 256, G1_SMEM_BYTES>>>(x);
    }

    cudaFuncSetAttribute(spmm1_fused_kernel,
                         cudaFuncAttributeMaxDynamicSharedMemorySize, SP1_SMEM_BYTES);
    spmm1_fused_kernel<<<NNODES / 8, 256, SP1_SMEM_BYTES>>>(b1, W2);

    spmm2_csr_kernel<<<NNODES / 8, 256>>>(b2, out);
}

// round 6
// speedup vs baseline: 1.6634x; 1.6634x over previous
#include <cuda_runtime.h>
#include <cuda_bf16.h>
#include <cstdint>
#include <math.h>

#define NNODES 100000
#define NEDGES 3200000
#define FIN    512
#define FHID   256
#define NCLS   40

// ---------------- device scratch ----------------
__device__ float g_H0[(size_t)NNODES * FHID];   // x @ W1
__device__ float g_H [(size_t)NNODES * FHID];   // relu(spmm(A,H0) + b1)
__device__ float g_P [(size_t)NNODES * NCLS];   // g_H @ W2
__device__ int   g_deg[NNODES];
__device__ int   g_rowptr[NNODES + 1];
__device__ int   g_fill[NNODES];
__device__ int   g_bsum[128];
__device__ int   g_boff[128];
__device__ int   g_ccol[NEDGES];
__device__ float g_cval[NEDGES];
__device__ int   g_is64;
// W1 packed bf16x2 hi/lo: [FIN/2 kpairs][FHID], elem = {lo16: k even, hi16: k odd}
__device__ uint32_t g_W1ph[(size_t)(FIN / 2) * FHID];
__device__ uint32_t g_W1pl[(size_t)(FIN / 2) * FHID];

// ---------------- helpers ----------------
__device__ __forceinline__ uint32_t pack_bf2(float x, float y) {
    __nv_bfloat162 t = __floats2bfloat162_rn(x, y);   // .x=lo16(x), .y=hi16(y)
    return *reinterpret_cast<uint32_t*>(&t);
}

__device__ __forceinline__ void split_bf2(float2 v, uint32_t& h, uint32_t& l) {
    __nv_bfloat162 hb = __floats2bfloat162_rn(v.x, v.y);
    h = *reinterpret_cast<uint32_t*>(&hb);
    float hx = __bfloat162float(hb.x);
    float hy = __bfloat162float(hb.y);
    l = pack_bf2(v.x - hx, v.y - hy);
}

__device__ __forceinline__ void mma_bf16(float* d, const uint32_t* a, const uint32_t* b) {
    asm volatile(
      "mma.sync.aligned.m16n8k16.row.col.f32.bf16.bf16.f32 "
      "{%0,%1,%2,%3}, {%4,%5,%6,%7}, {%8,%9}, {%0,%1,%2,%3};\n"
      : "+f"(d[0]), "+f"(d[1]), "+f"(d[2]), "+f"(d[3])
      : "r"(a[0]), "r"(a[1]), "r"(a[2]), "r"(a[3]), "r"(b[0]), "r"(b[1]));
}

// ---------------- edge index width detection ----------------
__global__ void detect_kernel(const void* rowp) {
    if (threadIdx.x == 0 && blockIdx.x == 0) {
        const int* p = (const int*)rowp;
        int is64 = 1;
        for (int i = 0; i < 128; i++) {
            if (p[2 * i + 1] != 0) { is64 = 0; break; }
        }
        g_is64 = is64;
    }
}

__device__ __forceinline__ int load_idx(const void* p, int i, int is64) {
    return is64 ? (int)((const long long*)p)[i] : ((const int*)p)[i];
}

// ---------------- CSR build ----------------
__global__ void zero_deg_kernel() {
    int i = blockIdx.x * 1024 + threadIdx.x;
    if (i < NNODES) g_deg[i] = 0;
}

__global__ __launch_bounds__(256) void hist_kernel(const void* rowp) {
    int i = blockIdx.x * 256 + threadIdx.x;
    if (i >= NEDGES) return;
    int r = load_idx(rowp, i, g_is64);
    atomicAdd(&g_deg[r], 1);
}

__global__ __launch_bounds__(1024) void scan_k1_kernel() {
    __shared__ int sh[1024];
    int t = threadIdx.x;
    int i = blockIdx.x * 1024 + t;
    sh[t] = (i < NNODES) ? g_deg[i] : 0;
    __syncthreads();
    for (int off = 512; off > 0; off >>= 1) {
        if (t < off) sh[t] += sh[t + off];
        __syncthreads();
    }
    if (t == 0) g_bsum[blockIdx.x] = sh[0];
}

__global__ void scan_k2_kernel(int nblocks) {
    __shared__ int sh[128];
    int t = threadIdx.x;
    int x = (t < nblocks) ? g_bsum[t] : 0;
    sh[t] = x;
    __syncthreads();
    for (int off = 1; off < 128; off <<= 1) {
        int v = (t >= off) ? sh[t - off] : 0;
        __syncthreads();
        sh[t] += v;
        __syncthreads();
    }
    if (t < nblocks) g_boff[t] = sh[t] - x;
    if (t == 0) g_rowptr[NNODES] = NEDGES;
}

__global__ __launch_bounds__(1024) void scan_k3_kernel() {
    __shared__ int sh[1024];
    int t = threadIdx.x;
    int i = blockIdx.x * 1024 + t;
    int x = (i < NNODES) ? g_deg[i] : 0;
    sh[t] = x;
    __syncthreads();
    for (int off = 1; off < 1024; off <<= 1) {
        int v = (t >= off) ? sh[t - off] : 0;
        __syncthreads();
        sh[t] += v;
        __syncthreads();
    }
    if (i < NNODES) {
        int excl = sh[t] - x + g_boff[blockIdx.x];
        g_rowptr[i] = excl;
        g_fill[i]   = excl;
    }
}

__global__ __launch_bounds__(256) void scatter_kernel(const void* rowp, const void* colp,
                                                      const float* __restrict__ val) {
    int i = blockIdx.x * 256 + threadIdx.x;
    if (i >= NEDGES) return;
    int is64 = g_is64;
    int r = load_idx(rowp, i, is64);
    int c = load_idx(colp, i, is64);
    int pos = atomicAdd(&g_fill[r], 1);
    g_ccol[pos] = c;
    g_cval[pos] = val[i];
}

// ---------------- W1 bf16 hi/lo packed pre-split ------------------------
__global__ __launch_bounds__(256) void w1cvt_kernel(const float* __restrict__ W1) {
    int i = blockIdx.x * 256 + threadIdx.x;
    if (i >= (FIN / 2) * FHID) return;
    int kp = i / FHID, n = i % FHID;
    float v0 = W1[(size_t)(2 * kp) * FHID + n];
    float v1 = W1[(size_t)(2 * kp + 1) * FHID + n];
    uint32_t h, l;
    split_bf2(make_float2(v0, v1), h, l);
    g_W1ph[i] = h;
    g_W1pl[i] = l;
}

// ---------------- GEMM1 (bf16 split, m16n8k16) --------------------------
// g_H0 = x @ W1, M=100000, K=512, N=256. Block 128x128, BK=16, 8 warps.
#define ASTRIDE 20
#define BSTRIDE 136

__global__ __launch_bounds__(256) void gemm1_bf16_kernel(const float* __restrict__ A) {
    __shared__ float    As[2][128 * ASTRIDE];
    __shared__ uint32_t Bh[2][8 * BSTRIDE];
    __shared__ uint32_t Bl[2][8 * BSTRIDE];

    const int tid  = threadIdx.x;
    const int lane = tid & 31;
    const int wid  = tid >> 5;
    const int wm   = wid & 3;       // 0..3  (M)
    const int wn   = wid >> 2;      // 0..1  (N)
    const int bm   = blockIdx.y * 128;
    const int bn   = blockIdx.x * 128;

    const int g  = lane >> 2;       // 0..7
    const int tg = lane & 3;        // 0..3

    float acc[2][8][4];
    #pragma unroll
    for (int i = 0; i < 2; i++)
        #pragma unroll
        for (int j = 0; j < 8; j++)
            #pragma unroll
            for (int q = 0; q < 4; q++) acc[i][j][q] = 0.f;

    float4 aReg[2];
    uint4  bRegH, bRegL;

    const int ldKp = tid >> 5;            // 0..7  (kpair within chunk)
    const int ldN4 = (tid & 31) * 4;      // 0..124

    // prologue: tile 0
    #pragma unroll
    for (int i = 0; i < 2; i++) {
        int f = tid + i * 256;
        int row = f >> 2, c4 = f & 3;
        float4 v = make_float4(0.f, 0.f, 0.f, 0.f);
        if (bm + row < NNODES)
            v = *(const float4*)(A + (size_t)(bm + row) * FIN + c4 * 4);
        *(float4*)(&As[0][row * ASTRIDE + c4 * 4]) = v;
    }
    {
        const size_t gi = (size_t)ldKp * FHID + bn + ldN4;
        *(uint4*)(&Bh[0][ldKp * BSTRIDE + ldN4]) = *(const uint4*)(g_W1ph + gi);
        *(uint4*)(&Bl[0][ldKp * BSTRIDE + ldN4]) = *(const uint4*)(g_W1pl + gi);
    }
    __syncthreads();

    const int NITER = FIN / 16;   // 32
    for (int it = 0; it < NITER; it++) {
        int s = it & 1;
        const float*    aS = As[s];
        const uint32_t* bH = Bh[s];
        const uint32_t* bL = Bl[s];

        // prefetch next tile into regs
        if (it + 1 < NITER) {
            int k0 = (it + 1) * 16;
            #pragma unroll
            for (int i = 0; i < 2; i++) {
                int f = tid + i * 256;
                int row = f >> 2, c4 = f & 3;
                aReg[i] = make_float4(0.f, 0.f, 0.f, 0.f);
                if (bm + row < NNODES)
                    aReg[i] = *(const float4*)(A + (size_t)(bm + row) * FIN + k0 + c4 * 4);
            }
            const size_t gi = (size_t)((it + 1) * 8 + ldKp) * FHID + bn + ldN4;
            bRegH = *(const uint4*)(g_W1ph + gi);
            bRegL = *(const uint4*)(g_W1pl + gi);
        }

        // A fragments (hi/lo bf16x2) for both m-tiles
        uint32_t ah[2][4], al[2][4];
        #pragma unroll
        for (int mt = 0; mt < 2; mt++) {
            int r0 = wm * 32 + mt * 16 + g;
            float2 p0 = *(const float2*)&aS[r0 * ASTRIDE + 2 * tg];
            float2 p1 = *(const float2*)&aS[(r0 + 8) * ASTRIDE + 2 * tg];
            float2 p2 = *(const float2*)&aS[r0 * ASTRIDE + 2 * tg + 8];
            float2 p3 = *(const float2*)&aS[(r0 + 8) * ASTRIDE + 2 * tg + 8];
            split_bf2(p0, ah[mt][0], al[mt][0]);
            split_bf2(p1, ah[mt][1], al[mt][1]);
            split_bf2(p2, ah[mt][2], al[mt][2]);
            split_bf2(p3, ah[mt][3], al[mt][3]);
        }

        #pragma unroll
        for (int nt = 0; nt < 8; nt++) {
            int n = wn * 64 + nt * 8 + g;
            uint32_t bh[2], bl[2];
            bh[0] = bH[tg * BSTRIDE + n];
            bh[1] = bH[(tg + 4) * BSTRIDE + n];
            bl[0] = bL[tg * BSTRIDE + n];
            bl[1] = bL[(tg + 4) * BSTRIDE + n];
            #pragma unroll
            for (int mt = 0; mt < 2; mt++) {
                mma_bf16(acc[mt][nt], ah[mt], bl);
                mma_bf16(acc[mt][nt], al[mt], bh);
                mma_bf16(acc[mt][nt], ah[mt], bh);
            }
        }

        // store next tile
        if (it + 1 < NITER) {
            int ns = (it + 1) & 1;
            #pragma unroll
            for (int i = 0; i < 2; i++) {
                int f = tid + i * 256;
                int row = f >> 2, c4 = f & 3;
                *(float4*)(&As[ns][row * ASTRIDE + c4 * 4]) = aReg[i];
            }
            *(uint4*)(&Bh[ns][ldKp * BSTRIDE + ldN4]) = bRegH;
            *(uint4*)(&Bl[ns][ldKp * BSTRIDE + ldN4]) = bRegL;
            __syncthreads();
        }
    }

    // epilogue
    #pragma unroll
    for (int mt = 0; mt < 2; mt++) {
        int r0 = bm + wm * 32 + mt * 16 + g;
        #pragma unroll
        for (int nt = 0; nt < 8; nt++) {
            int cc = bn + wn * 64 + nt * 8 + 2 * tg;
            if (r0 < NNODES)
                *(float2*)(g_H0 + (size_t)r0 * FHID + cc) =
                    make_float2(acc[mt][nt][0], acc[mt][nt][1]);
            if (r0 + 8 < NNODES)
                *(float2*)(g_H0 + (size_t)(r0 + 8) * FHID + cc) =
                    make_float2(acc[mt][nt][2], acc[mt][nt][3]);
        }
    }
}

// ---------------- SpMM1 (CSR, warp/row) + bias + relu -------------------
__global__ __launch_bounds__(256) void spmm1_csr_kernel(const float* __restrict__ b1) {
    int row  = blockIdx.x * 8 + (threadIdx.x >> 5);
    int lane = threadIdx.x & 31;
    int start = g_rowptr[row];
    int end   = g_rowptr[row + 1];

    float4 a0 = make_float4(0.f, 0.f, 0.f, 0.f);
    float4 a1 = make_float4(0.f, 0.f, 0.f, 0.f);

    for (int e0 = start; e0 < end; e0 += 32) {
        int m = min(32, end - e0);
        int   c = 0;
        float v = 0.f;
        if (lane < m) { c = g_ccol[e0 + lane]; v = g_cval[e0 + lane]; }
        for (int j = 0; j < m; j++) {
            int   cj = __shfl_sync(0xFFFFFFFFu, c, j);
            float vj = __shfl_sync(0xFFFFFFFFu, v, j);
            const float4* s = (const float4*)(g_H0 + (size_t)cj * FHID);
            float4 f0 = s[lane];
            float4 f1 = s[lane + 32];
            a0.x = fmaf(vj, f0.x, a0.x); a0.y = fmaf(vj, f0.y, a0.y);
            a0.z = fmaf(vj, f0.z, a0.z); a0.w = fmaf(vj, f0.w, a0.w);
            a1.x = fmaf(vj, f1.x, a1.x); a1.y = fmaf(vj, f1.y, a1.y);
            a1.z = fmaf(vj, f1.z, a1.z); a1.w = fmaf(vj, f1.w, a1.w);
        }
    }

    const float4* bb = (const float4*)b1;
    float4 t0 = bb[lane], t1 = bb[lane + 32];
    a0.x = fmaxf(a0.x + t0.x, 0.f); a0.y = fmaxf(a0.y + t0.y, 0.f);
    a0.z = fmaxf(a0.z + t0.z, 0.f); a0.w = fmaxf(a0.w + t0.w, 0.f);
    a1.x = fmaxf(a1.x + t1.x, 0.f); a1.y = fmaxf(a1.y + t1.y, 0.f);
    a1.z = fmaxf(a1.z + t1.z, 0.f); a1.w = fmaxf(a1.w + t1.w, 0.f);

    float4* d = (float4*)(g_H + (size_t)row * FHID);
    d[lane]      = a0;
    d[lane + 32] = a1;
}

// ---------------- GEMM2: g_P = g_H @ W2  (K=256, N=40) ------------------
#define W2STRIDE 260
__global__ __launch_bounds__(256) void gemm2_kernel(const float* __restrict__ W2) {
    __shared__ float shWT[NCLS * W2STRIDE];

    const int tid = threadIdx.x;
    for (int idx = tid; idx < FHID * NCLS; idx += 256) {
        int k = idx / NCLS, c = idx % NCLS;
        shWT[c * W2STRIDE + k] = W2[idx];
    }
    __syncthreads();

    const int rp = tid >> 3;
    const int c0 = (tid & 7) * 5;
    int r0 = blockIdx.x * 64 + rp * 2;
    int r1 = r0 + 1;
    bool v0 = r0 < NNODES, v1 = r1 < NNODES;
    int r0c = v0 ? r0 : NNODES - 1;
    int r1c = v1 ? r1 : NNODES - 1;

    const float4* h0 = (const float4*)(g_H + (size_t)r0c * FHID);
    const float4* h1 = (const float4*)(g_H + (size_t)r1c * FHID);

    float acc0[5] = {0.f, 0.f, 0.f, 0.f, 0.f};
    float acc1[5] = {0.f, 0.f, 0.f, 0.f, 0.f};

    #pragma unroll 4
    for (int kq = 0; kq < FHID / 4; kq++) {
        float4 ha = h0[kq];
        float4 hb = h1[kq];
        #pragma unroll
        for (int j = 0; j < 5; j++) {
            float4 w = *(const float4*)&shWT[(c0 + j) * W2STRIDE + kq * 4];
            acc0[j] = fmaf(ha.x, w.x, acc0[j]); acc0[j] = fmaf(ha.y, w.y, acc0[j]);
            acc0[j] = fmaf(ha.z, w.z, acc0[j]); acc0[j] = fmaf(ha.w, w.w, acc0[j]);
            acc1[j] = fmaf(hb.x, w.x, acc1[j]); acc1[j] = fmaf(hb.y, w.y, acc1[j]);
            acc1[j] = fmaf(hb.z, w.z, acc1[j]); acc1[j] = fmaf(hb.w, w.w, acc1[j]);
        }
    }

    if (v0) {
        float* p = g_P + (size_t)r0 * NCLS + c0;
        #pragma unroll
        for (int j = 0; j < 5; j++) p[j] = acc0[j];
    }
    if (v1) {
        float* p = g_P + (size_t)r1 * NCLS + c0;
        #pragma unroll
        for (int j = 0; j < 5; j++) p[j] = acc1[j];
    }
}

// ---------------- SpMM2 (CSR, warp/row) + bias + log_softmax ------------
__global__ __launch_bounds__(256) void spmm2_csr_kernel(const float* __restrict__ b2,
                                                        float* __restrict__ out) {
    int row  = blockIdx.x * 8 + (threadIdx.x >> 5);
    int lane = threadIdx.x & 31;
    int start = g_rowptr[row];
    int end   = g_rowptr[row + 1];

    float acc0 = 0.f, acc1 = 0.f;

    for (int e0 = start; e0 < end; e0 += 32) {
        int m = min(32, end - e0);
        int   c = 0;
        float v = 0.f;
        if (lane < m) { c = g_ccol[e0 + lane]; v = g_cval[e0 + lane]; }
        for (int j = 0; j < m; j++) {
            int   cj = __shfl_sync(0xFFFFFFFFu, c, j);
            float vj = __shfl_sync(0xFFFFFFFFu, v, j);
            const float* p = g_P + (size_t)cj * NCLS;
            float p0 = p[lane];
            float p1 = (lane < 8) ? p[32 + lane] : 0.f;
            acc0 = fmaf(vj, p0, acc0);
            acc1 = fmaf(vj, p1, acc1);
        }
    }

    float v0 = acc0 + b2[lane];
    float v1 = (lane < 8) ? (acc1 + b2[32 + lane]) : -INFINITY;

    float mx = fmaxf(v0, v1);
    #pragma unroll
    for (int off = 16; off > 0; off >>= 1)
        mx = fmaxf(mx, __shfl_xor_sync(0xFFFFFFFFu, mx, off));

    float s = expf(v0 - mx) + ((lane < 8) ? expf(v1 - mx) : 0.f);
    #pragma unroll
    for (int off = 16; off > 0; off >>= 1)
        s += __shfl_xor_sync(0xFFFFFFFFu, s, off);

    float ls = mx + logf(s);
    float* o = out + (size_t)row * NCLS;
    o[lane] = v0 - ls;
    if (lane < 8) o[32 + lane] = v1 - ls;
}

// ---------------- launch ----------------
extern "C" void kernel_launch(void* const* d_in, const int* in_sizes, int n_in,
                              void* d_out, int out_size) {
    const float* x    = (const float*)d_in[0];
    const void*  erow = d_in[1];
    const void*  ecol = d_in[2];
    const float* eval = (const float*)d_in[3];
    const float* W1   = (const float*)d_in[4];
    const float* b1   = (const float*)d_in[5];
    const float* W2   = (const float*)d_in[6];
    const float* b2   = (const float*)d_in[7];
    float* out = (float*)d_out;

    const int nchunks = (NNODES + 1023) / 1024;

    detect_kernel<<<1, 32>>>(erow);
    zero_deg_kernel<<<nchunks, 1024>>>();
    hist_kernel<<<NEDGES / 256, 256>>>(erow);
    scan_k1_kernel<<<nchunks, 1024>>>();
    scan_k2_kernel<<<1, 128>>>(nchunks);
    scan_k3_kernel<<<nchunks, 1024>>>();
    scatter_kernel<<<NEDGES / 256, 256>>>(erow, ecol, eval);

    w1cvt_kernel<<<((FIN / 2) * FHID + 255) / 256, 256>>>(W1);

    {
        dim3 grid(FHID / 128, (NNODES + 127) / 128);  // (2, 782)
        gemm1_bf16_kernel<<<grid, 256>>>(x);
    }

    spmm1_csr_kernel<<<NNODES / 8, 256>>>(b1);
    gemm2_kernel<<<(NNODES + 63) / 64, 256>>>(W2);
    spmm2_csr_kernel<<<NNODES / 8, 256>>>(b2, out);
}